// round 8
// baseline (speedup 1.0000x reference)
#include <cuda_runtime.h>
#include <cuda_fp16.h>
#include <cstdint>

// ---------------- problem constants ----------------
#define NT    8
#define RK    48
#define DIM   768
#define BATCH 32
#define CIN   256
#define COUT  256
#define HH    56
#define WW    56
#define HW    3136
#define KTOT  2304            // Cin*9, reordered as tap*256+ci
#define WELEM (COUT*KTOT)     // 589824
#define SCALING 2.0f
#define PWH   64              // padded row width in halves (128B rows)
#define PH    58
#define PPLANE (PH*PWH)       // 3712

// ---------------- scratch (device globals) ----------------
__device__ float  g_stack[NT * DIM * DIM];                 // [t][f], f = o*2304+ci*9+tap
__device__ __half g_agg[(long)BATCH * WELEM];              // [b][o][tap*256+ci], fp16
__device__ __half g_xpad[3L * BATCH * CIN * PPLANE];       // [kw][b][ci][58][64], fp16

__device__ __forceinline__ uint32_t smem_u32(const void* p) {
    uint32_t a;
    asm("{ .reg .u64 t; cvta.to.shared.u64 t, %1; cvt.u32.u64 %0, t; }" : "=r"(a) : "l"(p));
    return a;
}
__device__ __forceinline__ void cp16(uint32_t dst, const void* src) {
    asm volatile("cp.async.cg.shared.global [%0], [%1], 16;" :: "r"(dst), "l"(src));
}
__device__ __forceinline__ void ldsmA(uint32_t* r, uint32_t addr) {
    asm volatile("ldmatrix.sync.aligned.m8n8.x4.shared.b16 {%0,%1,%2,%3}, [%4];"
                 : "=r"(r[0]), "=r"(r[1]), "=r"(r[2]), "=r"(r[3]) : "r"(addr));
}
__device__ __forceinline__ void ldsmBT(uint32_t* r, uint32_t addr) {
    asm volatile("ldmatrix.sync.aligned.m8n8.x2.trans.shared.b16 {%0,%1}, [%2];"
                 : "=r"(r[0]), "=r"(r[1]) : "r"(addr));
}
__device__ __forceinline__ void hmma(float* d, const uint32_t* a, const uint32_t* b) {
    asm volatile(
        "mma.sync.aligned.m16n8k16.row.col.f32.f16.f16.f32 "
        "{%0,%1,%2,%3}, {%4,%5,%6,%7}, {%8,%9}, {%0,%1,%2,%3};"
        : "+f"(d[0]), "+f"(d[1]), "+f"(d[2]), "+f"(d[3])
        : "r"(a[0]), "r"(a[1]), "r"(a[2]), "r"(a[3]), "r"(b[0]), "r"(b[1]));
}

// ---------------------------------------------------------------------------
// Kernel P: kw-shifted zero-padded fp16 copies of x. grid (8192, 3).
// ---------------------------------------------------------------------------
__global__ void pad_kernel(const float* __restrict__ x) {
    int plane = blockIdx.x;                 // b*256+ci
    int kw    = blockIdx.y;
    const float* src = x + (long)plane * HW;
    __half* dst = g_xpad + ((long)kw * BATCH * CIN + plane) * PPLANE;
    for (int i8 = threadIdx.x; i8 < PPLANE / 8; i8 += 256) {
        int y   = i8 >> 3;
        int xs0 = (i8 & 7) * 8;
        __half2 h[4];
#pragma unroll
        for (int p = 0; p < 4; p++) {
            float v0 = 0.f, v1 = 0.f;
            if (y >= 1 && y <= HH) {
                const float* row = src + (y - 1) * WW;
                int xc = xs0 + p * 2 + kw - 1;
                if (xc >= 0 && xc < WW) v0 = row[xc];
                if (xc + 1 >= 0 && xc + 1 < WW) v1 = row[xc + 1];
            }
            h[p] = __floats2half2_rn(v0, v1);
        }
        *(float4*)(dst + i8 * 8) = *(float4*)h;
    }
}

// ---------------------------------------------------------------------------
// Kernel A: stack[t] = lora_B[t] (768x48) @ lora_A[t] (48x768)
// ---------------------------------------------------------------------------
__global__ void synth_stack_kernel(const float* __restrict__ lora_A,
                                   const float* __restrict__ lora_B) {
    int t    = blockIdx.z;
    int row0 = blockIdx.y * 32;
    int col0 = blockIdx.x * 128;
    __shared__ float Bs[32][RK + 1];
    __shared__ float As[RK][128];
    int tid = threadIdx.x;

    for (int i = tid; i < 32 * RK; i += 256) {
        int r = i / RK, k = i % RK;
        Bs[r][k] = lora_B[((long)t * DIM + row0 + r) * RK + k];
    }
    for (int i = tid; i < RK * 32; i += 256) {
        int k = i / 32, c4 = i % 32;
        *(float4*)&As[k][c4 * 4] =
            *(const float4*)(lora_A + ((long)t * RK + k) * DIM + col0 + c4 * 4);
    }
    __syncthreads();

    int r  = tid >> 3;
    int c0 = (tid & 7) * 16;
    float acc[16];
#pragma unroll
    for (int j = 0; j < 16; j++) acc[j] = 0.f;
#pragma unroll
    for (int k = 0; k < RK; k++) {
        float bv = Bs[r][k];
#pragma unroll
        for (int j = 0; j < 16; j++) acc[j] += bv * As[k][c0 + j];
    }
    float* dst = &g_stack[((long)t * DIM + row0 + r) * DIM + col0 + c0];
#pragma unroll
    for (int j4 = 0; j4 < 4; j4++)
        *(float4*)(dst + j4 * 4) = make_float4(acc[j4*4], acc[j4*4+1], acc[j4*4+2], acc[j4*4+3]);
}

// ---------------------------------------------------------------------------
// Kernel B: block per (o, b-group of 8). Stage stack rows + w through smem.
// grid (COUT, 4), block 256, dyn smem 9*2304*4 = 82944 B.
// ---------------------------------------------------------------------------
__global__ void build_agg_kernel(const float* __restrict__ alphas,
                                 const float* __restrict__ conv_w) {
    extern __shared__ float sh[];          // [8][2304] stack, then [2304] w
    __shared__ float sal[BATCH * NT];
    const int tid = threadIdx.x;
    const int o   = blockIdx.x;
    const int b0  = blockIdx.y * 8;
    sal[tid] = alphas[tid];

#pragma unroll
    for (int t = 0; t < NT; t++)
        for (int i = tid; i < KTOT; i += 256)
            sh[t * KTOT + i] = g_stack[(long)t * WELEM + (long)o * KTOT + i];
    for (int i = tid; i < KTOT; i += 256)
        sh[NT * KTOT + i] = conv_w[(long)o * KTOT + i];
    __syncthreads();

    float s[NT][9], wv[9];
#pragma unroll
    for (int tap = 0; tap < 9; tap++) {
        wv[tap] = sh[NT * KTOT + tid * 9 + tap];
#pragma unroll
        for (int t = 0; t < NT; t++) s[t][tap] = sh[t * KTOT + tid * 9 + tap];
    }

    __half* outb = g_agg + (long)o * KTOT + tid;
#pragma unroll
    for (int bi = 0; bi < 8; bi++) {
        int b = b0 + bi;
        float al[NT];
#pragma unroll
        for (int t = 0; t < NT; t++) al[t] = SCALING * sal[b * NT + t];
#pragma unroll
        for (int tap = 0; tap < 9; tap++) {
            float a = wv[tap];
#pragma unroll
            for (int t = 0; t < NT; t++) a += al[t] * s[t][tap];
            outb[(long)b * WELEM + tap * 256] = __float2half_rn(a);
        }
    }
}

// ---------------------------------------------------------------------------
// Kernel C: fp16 mma.sync m16n8k16 implicit-GEMM conv.
// CTA: 256 threads (8 warps, 4m x 2n), M=256, N=112, warp tile 64x56.
// K=2304 in 36 chunks of 64; 3-stage cp.async pipeline; fragment
// double-buffering (af per-ms, bf per-ks) to overlap LDSM with HMMA.
// ---------------------------------------------------------------------------
#define KC      64
#define NCHUNK  36
#define ASTRB   144                     // A row stride bytes (72 halves)
#define ABYTES  (256 * ASTRB)           // 36864
#define BSTRB   272                     // B ci stride bytes
#define BBYTES  (KC * BSTRB)            // 17408
#define STBYTES (ABYTES + BBYTES)       // 54272
#define STAGES  3
#define CONV_SMEM (STAGES * STBYTES)    // 162816

__global__ __launch_bounds__(256, 1)
void conv_mma_kernel(float* __restrict__ out) {
    extern __shared__ uint32_t sm[];
    const uint32_t smb = smem_u32(sm);

    const int tid  = threadIdx.x;
    const int lane = tid & 31;
    const int wid  = tid >> 5;
    const int wm   = wid >> 1;      // 0..3: m offset wm*64
    const int wn   = wid & 1;       // 0..1: image row within 2-row tile
    const int q    = lane >> 2;
    const int t4   = lane & 3;

    const int b  = blockIdx.y;
    const int nt = blockIdx.x;      // 0..27
    const int y0 = nt * 2;

    const __half* agg_b = g_agg + (long)b * WELEM;

    const int gA = lane >> 3, rA = lane & 7;
    const uint32_t a_lane = (uint32_t)(((gA & 1) * 8 + rA) * ASTRB + (gA >> 1) * 16);
    const uint32_t b_lane = (uint32_t)((lane & 15) * BSTRB + wn * 128);

    auto issue = [&](int c, int buf) {
        uint32_t sa = smb + buf * STBYTES;
#pragma unroll
        for (int j = 0; j < 8; j++) {
            int idx = tid + j * 256;
            int m = idx >> 3, seg = idx & 7;
            cp16(sa + m * ASTRB + seg * 16,
                 agg_b + (long)m * KTOT + c * KC + seg * 8);
        }
        int tap = c >> 2;
        int ci0 = (c & 3) * 64;
        int kh = tap / 3, kw = tap % 3;
        const __half* gsrc = g_xpad
            + ((long)(kw * BATCH + b) * CIN + ci0) * PPLANE + (y0 + kh) * PWH;
        uint32_t bb = sa + ABYTES;
#pragma unroll
        for (int j = 0; j < 4; j++) {
            int idx = tid + j * 256;
            int rowid = idx >> 3, seg = idx & 7;
            int ci = rowid >> 1, yy = rowid & 1;
            cp16(bb + ci * BSTRB + yy * 128 + seg * 16,
                 gsrc + (long)ci * PPLANE + yy * PWH + seg * 8);
        }
        asm volatile("cp.async.commit_group;" ::: "memory");
    };

    issue(0, 0);
    issue(1, 1);

    float acc[4][7][4];
#pragma unroll
    for (int i = 0; i < 4; i++)
#pragma unroll
        for (int j = 0; j < 7; j++)
#pragma unroll
            for (int e = 0; e < 4; e++) acc[i][j][e] = 0.f;

    for (int c = 0; c < NCHUNK; c++) {
        asm volatile("cp.async.wait_group 1;" ::: "memory");
        __syncthreads();

        const int buf = c % 3;
        const uint32_t stage = smb + buf * STBYTES;
        const uint32_t aw = stage + (wm * 64) * ASTRB + a_lane;
        const uint32_t bw = stage + ABYTES + b_lane;

        uint32_t bf[2][7][2];
        uint32_t af[2][4];

        // prefetch ks=0 fragments first so MMA starts ASAP
#pragma unroll
        for (int ns = 0; ns < 7; ns++) ldsmBT(bf[0][ns], bw + ns * 16);
        ldsmA(af[0], aw);

        // then issue cp.async for chunk c+2 (needed 2 chunks later)
        if (c + 2 < NCHUNK) issue(c + 2, (c + 2) % 3);
        else asm volatile("cp.async.commit_group;" ::: "memory");

#pragma unroll
        for (int ks = 0; ks < 4; ks++) {
            const int kk = ks * 16;
            // prefetch next ks's B fragments (hidden under 4 ms-groups of MMA)
            if (ks < 3) {
#pragma unroll
                for (int ns = 0; ns < 7; ns++)
                    ldsmBT(bf[(ks + 1) & 1][ns], bw + (kk + 16) * BSTRB + ns * 16);
            }
#pragma unroll
            for (int ms = 0; ms < 4; ms++) {
                // prefetch next A fragment (hidden under this ms's 7 HMMAs)
                if (ms < 3)
                    ldsmA(af[(ms + 1) & 1], aw + (ms + 1) * (16 * ASTRB) + kk * 2);
                else if (ks < 3)
                    ldsmA(af[0], aw + (kk + 16) * 2);
#pragma unroll
                for (int ns = 0; ns < 7; ns++)
                    hmma(acc[ms][ns], af[ms & 1], bf[ks & 1][ns]);
            }
        }
    }

    // ---- epilogue ----
    {
        const int nbase = nt * 112 + wn * 56;
#pragma unroll
        for (int ms = 0; ms < 4; ms++) {
            int row0 = wm * 64 + ms * 16 + q;
#pragma unroll
            for (int ns = 0; ns < 7; ns++) {
                int np = nbase + ns * 8 + t4 * 2;
                *(float2*)(out + ((long)(b * COUT + row0)) * HW + np) =
                    make_float2(acc[ms][ns][0], acc[ms][ns][1]);
                *(float2*)(out + ((long)(b * COUT + row0 + 8)) * HW + np) =
                    make_float2(acc[ms][ns][2], acc[ms][ns][3]);
            }
        }
    }
}

// ---------------------------------------------------------------------------
extern "C" void kernel_launch(void* const* d_in, const int* in_sizes, int n_in,
                              void* d_out, int out_size) {
    const float* x      = (const float*)d_in[0];
    const float* alphas = (const float*)d_in[1];
    const float* conv_w = (const float*)d_in[2];
    const float* lora_A = (const float*)d_in[3];
    const float* lora_B = (const float*)d_in[4];
    float* out = (float*)d_out;

    dim3 gP(BATCH * CIN, 3);
    pad_kernel<<<gP, 256>>>(x);

    dim3 gA(DIM / 128, DIM / 32, NT);
    synth_stack_kernel<<<gA, 256>>>(lora_A, lora_B);

    const int aggSmem = (NT + 1) * KTOT * 4;   // 82944
    cudaFuncSetAttribute(build_agg_kernel,
                         cudaFuncAttributeMaxDynamicSharedMemorySize, aggSmem);
    dim3 gB(COUT, 4);
    build_agg_kernel<<<gB, 256, aggSmem>>>(alphas, conv_w);

    cudaFuncSetAttribute(conv_mma_kernel,
                         cudaFuncAttributeMaxDynamicSharedMemorySize, CONV_SMEM);
    dim3 gC(28, BATCH);
    conv_mma_kernel<<<gC, 256, CONV_SMEM>>>(out);
}

// round 9
// speedup vs baseline: 1.0441x; 1.0441x over previous
#include <cuda_runtime.h>
#include <cuda_fp16.h>
#include <cstdint>

// ---------------- problem constants ----------------
#define NT    8
#define RK    48
#define DIM   768
#define BATCH 32
#define CIN   256
#define COUT  256
#define HH    56
#define WW    56
#define HW    3136
#define KTOT  2304            // Cin*9, reordered as tap*256+ci
#define WELEM (COUT*KTOT)     // 589824
#define SCALING 2.0f
#define PWH   64              // padded row width in halves (128B rows)
#define PH    58
#define PPLANE (PH*PWH)       // 3712

// ---------------- scratch (device globals) ----------------
__device__ float  g_stack[NT * DIM * DIM];                 // [t][f], f = o*2304+ci*9+tap
__device__ __half g_agg[(long)BATCH * WELEM];              // [b][o][tap*256+ci], fp16
__device__ __half g_xpad[3L * BATCH * CIN * PPLANE];       // [kw][b][ci][58][64], fp16

__device__ __forceinline__ uint32_t smem_u32(const void* p) {
    uint32_t a;
    asm("{ .reg .u64 t; cvta.to.shared.u64 t, %1; cvt.u32.u64 %0, t; }" : "=r"(a) : "l"(p));
    return a;
}
__device__ __forceinline__ void cp16(uint32_t dst, const void* src) {
    asm volatile("cp.async.cg.shared.global [%0], [%1], 16;" :: "r"(dst), "l"(src));
}
__device__ __forceinline__ void ldsmA(uint32_t* r, uint32_t addr) {
    asm volatile("ldmatrix.sync.aligned.m8n8.x4.shared.b16 {%0,%1,%2,%3}, [%4];"
                 : "=r"(r[0]), "=r"(r[1]), "=r"(r[2]), "=r"(r[3]) : "r"(addr));
}
__device__ __forceinline__ void ldsmBT(uint32_t* r, uint32_t addr) {
    asm volatile("ldmatrix.sync.aligned.m8n8.x2.trans.shared.b16 {%0,%1}, [%2];"
                 : "=r"(r[0]), "=r"(r[1]) : "r"(addr));
}
__device__ __forceinline__ void hmma(float* d, const uint32_t* a, const uint32_t* b) {
    asm volatile(
        "mma.sync.aligned.m16n8k16.row.col.f32.f16.f16.f32 "
        "{%0,%1,%2,%3}, {%4,%5,%6,%7}, {%8,%9}, {%0,%1,%2,%3};"
        : "+f"(d[0]), "+f"(d[1]), "+f"(d[2]), "+f"(d[3])
        : "r"(a[0]), "r"(a[1]), "r"(a[2]), "r"(a[3]), "r"(b[0]), "r"(b[1]));
}

// ---------------------------------------------------------------------------
// Kernel P v3: stage x-plane into padded fp32 smem once, emit 3 kw-shifted
// fp16 copies. copy[kw][y'][xx'] = x[y'-1][xx'+kw-1] = sp[y'][xx'+kw].
// ---------------------------------------------------------------------------
__global__ void pad_kernel(const float* __restrict__ x) {
    __shared__ float sp[PH][68];            // cols -1..66 of x (zero outside)
    int plane = blockIdx.x;                 // b*256+ci
    const float* src = x + (long)plane * HW;
    int tid = threadIdx.x;

    for (int i = tid; i < PH * 68; i += 256) ((float*)sp)[i] = 0.f;
    __syncthreads();
    for (int i = tid; i < HW; i += 256) {
        int y = i / WW, c = i % WW;
        sp[y + 1][c + 1] = src[i];
    }
    __syncthreads();

#pragma unroll
    for (int kw = 0; kw < 3; kw++) {
        __half* dst = g_xpad + ((long)kw * BATCH * CIN + plane) * PPLANE;
        for (int i8 = tid; i8 < PPLANE / 8; i8 += 256) {
            int y   = i8 >> 3;
            int xs0 = (i8 & 7) * 8;
            __half2 h[4];
#pragma unroll
            for (int p = 0; p < 4; p++)
                h[p] = __floats2half2_rn(sp[y][xs0 + p * 2 + kw],
                                         sp[y][xs0 + p * 2 + 1 + kw]);
            *(float4*)(dst + i8 * 8) = *(float4*)h;
        }
    }
}

// ---------------------------------------------------------------------------
// Kernel A: stack[t] = lora_B[t] (768x48) @ lora_A[t] (48x768)
// ---------------------------------------------------------------------------
__global__ void synth_stack_kernel(const float* __restrict__ lora_A,
                                   const float* __restrict__ lora_B) {
    int t    = blockIdx.z;
    int row0 = blockIdx.y * 32;
    int col0 = blockIdx.x * 128;
    __shared__ float Bs[32][RK + 1];
    __shared__ float As[RK][128];
    int tid = threadIdx.x;

    for (int i = tid; i < 32 * RK; i += 256) {
        int r = i / RK, k = i % RK;
        Bs[r][k] = lora_B[((long)t * DIM + row0 + r) * RK + k];
    }
    for (int i = tid; i < RK * 32; i += 256) {
        int k = i / 32, c4 = i % 32;
        *(float4*)&As[k][c4 * 4] =
            *(const float4*)(lora_A + ((long)t * RK + k) * DIM + col0 + c4 * 4);
    }
    __syncthreads();

    int r  = tid >> 3;
    int c0 = (tid & 7) * 16;
    float acc[16];
#pragma unroll
    for (int j = 0; j < 16; j++) acc[j] = 0.f;
#pragma unroll
    for (int k = 0; k < RK; k++) {
        float bv = Bs[r][k];
#pragma unroll
        for (int j = 0; j < 16; j++) acc[j] += bv * As[k][c0 + j];
    }
    float* dst = &g_stack[((long)t * DIM + row0 + r) * DIM + col0 + c0];
#pragma unroll
    for (int j4 = 0; j4 < 4; j4++)
        *(float4*)(dst + j4 * 4) = make_float4(acc[j4*4], acc[j4*4+1], acc[j4*4+2], acc[j4*4+3]);
}

// ---------------------------------------------------------------------------
// Kernel B (R5 v2, measured-best): thread handles 2 consecutive reordered
// indices, half2 stores. agg[b][g] with g = o*2304 + tap*256 + ci,
// f = o*2304 + ci*9 + tap. grid WELEM/512, block 256.
// ---------------------------------------------------------------------------
__global__ void build_agg_kernel(const float* __restrict__ alphas,
                                 const float* __restrict__ conv_w) {
    __shared__ float sal[BATCH * NT];
    int tid = threadIdx.x;
    sal[tid] = alphas[tid];
    __syncthreads();

    long g0 = ((long)blockIdx.x * 256 + tid) * 2;
    int o   = (int)(g0 / KTOT);
    int r2  = (int)(g0 % KTOT);
    int tap = r2 >> 8;
    int ci  = r2 & 255;
    long f0 = (long)o * KTOT + ci * 9 + tap;
    long f1 = f0 + 9;

    float s0[NT], s1[NT];
#pragma unroll
    for (int t = 0; t < NT; t++) {
        s0[t] = g_stack[(long)t * WELEM + f0];
        s1[t] = g_stack[(long)t * WELEM + f1];
    }
    float w0 = conv_w[f0], w1 = conv_w[f1];

#pragma unroll 4
    for (int b = 0; b < BATCH; b++) {
        float a0 = w0, a1 = w1;
#pragma unroll
        for (int t = 0; t < NT; t++) {
            float al = SCALING * sal[b * NT + t];
            a0 += al * s0[t];
            a1 += al * s1[t];
        }
        *(__half2*)(g_agg + (long)b * WELEM + g0) = __floats2half2_rn(a0, a1);
    }
}

// ---------------------------------------------------------------------------
// Kernel C: fp16 mma.sync m16n8k16 implicit-GEMM conv.
// CTA: 256 threads (8 warps, 4m x 2n), M=256, N=112, warp tile 64x56.
// K=2304 in 18 chunks of 128; 2-stage cp.async, ONE barrier per chunk:
//   wait_group 0 ; syncthreads ; issue(c+1) ; compute(c)
// (sync at top guarantees all warps finished chunk c-1's buffer = (c+1)&1)
// ---------------------------------------------------------------------------
#define KC      128
#define NCHUNK  18
#define ASTRB   272                     // A row stride bytes (128 halves + 8 pad)
#define ABYTES  (256 * ASTRB)           // 69632
#define BSTRB   272                     // B ci stride bytes (2 rows x 128B + 16)
#define BBYTES  (KC * BSTRB)            // 34816
#define STBYTES (ABYTES + BBYTES)       // 104448
#define STAGES  2
#define CONV_SMEM (STAGES * STBYTES)    // 208896

__global__ __launch_bounds__(256, 1)
void conv_mma_kernel(float* __restrict__ out) {
    extern __shared__ uint32_t sm[];
    const uint32_t smb = smem_u32(sm);

    const int tid  = threadIdx.x;
    const int lane = tid & 31;
    const int wid  = tid >> 5;
    const int wm   = wid >> 1;      // 0..3: m offset wm*64
    const int wn   = wid & 1;       // 0..1: image row within 2-row tile
    const int q    = lane >> 2;
    const int t4   = lane & 3;

    const int b  = blockIdx.y;
    const int nt = blockIdx.x;      // 0..27
    const int y0 = nt * 2;

    const __half* agg_b = g_agg + (long)b * WELEM;

    const int gA = lane >> 3, rA = lane & 7;
    const uint32_t a_lane = (uint32_t)(((gA & 1) * 8 + rA) * ASTRB + (gA >> 1) * 16);
    const uint32_t b_lane = (uint32_t)((lane & 15) * BSTRB + wn * 128);

    auto issue = [&](int c, int buf) {
        uint32_t sa = smb + buf * STBYTES;
        // A: 256 rows x 256B = 4096 x 16B (16 per thread)
#pragma unroll
        for (int j = 0; j < 16; j++) {
            int idx = tid + j * 256;
            int m = idx >> 4, seg = idx & 15;
            cp16(sa + m * ASTRB + seg * 16,
                 agg_b + (long)m * KTOT + c * KC + seg * 8);
        }
        // B: 128 ci x 2 rows x 128B = 2048 x 16B (8 per thread)
        int tap = c >> 1;
        int ci0 = (c & 1) * 128;
        int kh = tap / 3, kw = tap % 3;
        const __half* gsrc = g_xpad
            + ((long)(kw * BATCH + b) * CIN + ci0) * PPLANE + (y0 + kh) * PWH;
        uint32_t bb = sa + ABYTES;
#pragma unroll
        for (int j = 0; j < 8; j++) {
            int idx = tid + j * 256;
            int rowid = idx >> 3, seg = idx & 7;
            int ci = rowid >> 1, yy = rowid & 1;
            cp16(bb + ci * BSTRB + yy * 128 + seg * 16,
                 gsrc + (long)ci * PPLANE + yy * PWH + seg * 8);
        }
        asm volatile("cp.async.commit_group;" ::: "memory");
    };

    issue(0, 0);

    float acc[4][7][4];
#pragma unroll
    for (int i = 0; i < 4; i++)
#pragma unroll
        for (int j = 0; j < 7; j++)
#pragma unroll
            for (int e = 0; e < 4; e++) acc[i][j][e] = 0.f;

    for (int c = 0; c < NCHUNK; c++) {
        asm volatile("cp.async.wait_group 0;" ::: "memory");
        __syncthreads();

        if (c + 1 < NCHUNK) issue(c + 1, (c + 1) & 1);

        const uint32_t stage = smb + (c & 1) * STBYTES;
        const uint32_t aw = stage + (wm * 64) * ASTRB + a_lane;
        const uint32_t bw = stage + ABYTES + b_lane;

        uint32_t bf[2][7][2];
        uint32_t af[2][4];

#pragma unroll
        for (int ns = 0; ns < 7; ns++) ldsmBT(bf[0][ns], bw + ns * 16);
        ldsmA(af[0], aw);

#pragma unroll
        for (int ks = 0; ks < 8; ks++) {
            const int kk = ks * 16;
            if (ks < 7) {
#pragma unroll
                for (int ns = 0; ns < 7; ns++)
                    ldsmBT(bf[(ks + 1) & 1][ns], bw + (kk + 16) * BSTRB + ns * 16);
            }
#pragma unroll
            for (int ms = 0; ms < 4; ms++) {
                if (ms < 3)
                    ldsmA(af[(ms + 1) & 1], aw + (ms + 1) * (16 * ASTRB) + kk * 2);
                else if (ks < 7)
                    ldsmA(af[0], aw + (kk + 16) * 2);
#pragma unroll
                for (int ns = 0; ns < 7; ns++)
                    hmma(acc[ms][ns], af[ms & 1], bf[ks & 1][ns]);
            }
        }
    }

    // ---- epilogue ----
    {
        const int nbase = nt * 112 + wn * 56;
#pragma unroll
        for (int ms = 0; ms < 4; ms++) {
            int row0 = wm * 64 + ms * 16 + q;
#pragma unroll
            for (int ns = 0; ns < 7; ns++) {
                int np = nbase + ns * 8 + t4 * 2;
                *(float2*)(out + ((long)(b * COUT + row0)) * HW + np) =
                    make_float2(acc[ms][ns][0], acc[ms][ns][1]);
                *(float2*)(out + ((long)(b * COUT + row0 + 8)) * HW + np) =
                    make_float2(acc[ms][ns][2], acc[ms][ns][3]);
            }
        }
    }
}

// ---------------------------------------------------------------------------
extern "C" void kernel_launch(void* const* d_in, const int* in_sizes, int n_in,
                              void* d_out, int out_size) {
    const float* x      = (const float*)d_in[0];
    const float* alphas = (const float*)d_in[1];
    const float* conv_w = (const float*)d_in[2];
    const float* lora_A = (const float*)d_in[3];
    const float* lora_B = (const float*)d_in[4];
    float* out = (float*)d_out;

    pad_kernel<<<BATCH * CIN, 256>>>(x);

    dim3 gA(DIM / 128, DIM / 32, NT);
    synth_stack_kernel<<<gA, 256>>>(lora_A, lora_B);

    build_agg_kernel<<<WELEM / 512, 256>>>(alphas, conv_w);

    cudaFuncSetAttribute(conv_mma_kernel,
                         cudaFuncAttributeMaxDynamicSharedMemorySize, CONV_SMEM);
    dim3 gC(28, BATCH);
    conv_mma_kernel<<<gC, 256, CONV_SMEM>>>(out);
}